// round 6
// baseline (speedup 1.0000x reference)
#include <cuda_runtime.h>
#include <cuda_bf16.h>
#include <math.h>

#define BATCH 2
#define SEQ   2048
#define DMODEL 1024
#define NHEADS 16
#define DK    64
#define NROWS (BATCH*SEQ)   // 4096

// ---------------- scratch (device globals; no allocation) ----------------
__device__ float g_Q[BATCH*NHEADS*SEQ*DK];   // [b][h][s][d]
__device__ float g_K[BATCH*NHEADS*SEQ*DK];
__device__ float g_V[BATCH*NHEADS*SEQ*DK];
__device__ float g_AO[NROWS*DMODEL];         // attention output, [n][1024]
__device__ float g_cos[SEQ*(DK/2)];
__device__ float g_sin[SEQ*(DK/2)];

// ---------------- RoPE tables ----------------
__global__ void rope_tables_kernel(const int* __restrict__ pos) {
    int i = blockIdx.x * blockDim.x + threadIdx.x;
    if (i >= SEQ * (DK/2)) return;
    int s = i >> 5;        // / 32
    int p = i & 31;
    float inv_freq = powf(10000.0f, -(2.0f * (float)p) / 64.0f);
    float ang = (float)pos[s] * inv_freq;
    g_cos[i] = cosf(ang);
    g_sin[i] = sinf(ang);
}

// ---------------- fused QKV projection GEMM ----------------
// C[n,o] = sum_d A[n,d] * W[o,d]   (A: 4096x1024, W: 1024x1024 row-major)
// blockIdx.z selects {Wq->g_Q (rope), Wk->g_K (rope), Wv->g_V}.
// Output scattered to [b][h][s][d].
__global__ __launch_bounds__(256) void qkv_gemm_kernel(
    const float* __restrict__ A,
    const float* __restrict__ Wq, const float* __restrict__ Wk, const float* __restrict__ Wv)
{
    __shared__ __align__(16) float As[8*128];
    __shared__ __align__(16) float Bs[8*128];

    const int which = blockIdx.z;
    const float* W = (which == 0) ? Wq : (which == 1) ? Wk : Wv;
    float* C = (which == 0) ? g_Q : (which == 1) ? g_K : g_V;
    const bool do_rope = (which < 2);

    const int t  = threadIdx.x;
    const int tx = t & 15, ty = t >> 4;
    const int rowBase = blockIdx.y * 128;
    const int colBase = blockIdx.x * 128;

    const int lr = t >> 1;        // 0..127
    const int lc = (t & 1) * 4;   // 0 or 4

    float acc[8][8];
#pragma unroll
    for (int i = 0; i < 8; i++)
#pragma unroll
        for (int j = 0; j < 8; j++) acc[i][j] = 0.0f;

    for (int k0 = 0; k0 < 1024; k0 += 8) {
        float4 av = *(const float4*)&A[(rowBase + lr) * 1024 + k0 + lc];
        float4 bv = *(const float4*)&W[(colBase + lr) * 1024 + k0 + lc];
        __syncthreads();
        As[(lc+0)*128 + lr] = av.x; As[(lc+1)*128 + lr] = av.y;
        As[(lc+2)*128 + lr] = av.z; As[(lc+3)*128 + lr] = av.w;
        Bs[(lc+0)*128 + lr] = bv.x; Bs[(lc+1)*128 + lr] = bv.y;
        Bs[(lc+2)*128 + lr] = bv.z; Bs[(lc+3)*128 + lr] = bv.w;
        __syncthreads();
#pragma unroll
        for (int k = 0; k < 8; k++) {
            float4 a0 = *(const float4*)&As[k*128 + ty*8];
            float4 a1 = *(const float4*)&As[k*128 + ty*8 + 4];
            float4 b0 = *(const float4*)&Bs[k*128 + tx*8];
            float4 b1 = *(const float4*)&Bs[k*128 + tx*8 + 4];
            float a[8] = {a0.x,a0.y,a0.z,a0.w,a1.x,a1.y,a1.z,a1.w};
            float b[8] = {b0.x,b0.y,b0.z,b0.w,b1.x,b1.y,b1.z,b1.w};
#pragma unroll
            for (int i = 0; i < 8; i++)
#pragma unroll
                for (int j = 0; j < 8; j++) acc[i][j] = fmaf(a[i], b[j], acc[i][j]);
        }
    }

#pragma unroll
    for (int i = 0; i < 8; i++) {
        int m  = rowBase + ty*8 + i;
        int b_ = m >> 11;          // /2048
        int s_ = m & 2047;
        float v[8];
#pragma unroll
        for (int j = 0; j < 8; j++) v[j] = acc[i][j];
        if (do_rope) {
#pragma unroll
            for (int j = 0; j < 8; j += 2) {
                int n = colBase + tx*8 + j;
                int p = (n & 63) >> 1;
                float c = g_cos[s_*32 + p];
                float sn = g_sin[s_*32 + p];
                float x1 = v[j], x2 = v[j+1];
                v[j]   = x1*c - x2*sn;
                v[j+1] = x1*sn + x2*c;
            }
        }
#pragma unroll
        for (int j = 0; j < 8; j++) {
            int n = colBase + tx*8 + j;
            int h = n >> 6, d = n & 63;
            C[(((b_ << 4) + h) * 2048 + s_) * 64 + d] = v[j];
        }
    }
}

// ---------------- output projection GEMM (plain row-major store) ----------------
__global__ __launch_bounds__(256) void out_gemm_kernel(
    const float* __restrict__ A, const float* __restrict__ W, float* __restrict__ C)
{
    __shared__ __align__(16) float As[8*128];
    __shared__ __align__(16) float Bs[8*128];

    const int t  = threadIdx.x;
    const int tx = t & 15, ty = t >> 4;
    const int rowBase = blockIdx.y * 128;
    const int colBase = blockIdx.x * 128;
    const int lr = t >> 1;
    const int lc = (t & 1) * 4;

    float acc[8][8];
#pragma unroll
    for (int i = 0; i < 8; i++)
#pragma unroll
        for (int j = 0; j < 8; j++) acc[i][j] = 0.0f;

    for (int k0 = 0; k0 < 1024; k0 += 8) {
        float4 av = *(const float4*)&A[(rowBase + lr) * 1024 + k0 + lc];
        float4 bv = *(const float4*)&W[(colBase + lr) * 1024 + k0 + lc];
        __syncthreads();
        As[(lc+0)*128 + lr] = av.x; As[(lc+1)*128 + lr] = av.y;
        As[(lc+2)*128 + lr] = av.z; As[(lc+3)*128 + lr] = av.w;
        Bs[(lc+0)*128 + lr] = bv.x; Bs[(lc+1)*128 + lr] = bv.y;
        Bs[(lc+2)*128 + lr] = bv.z; Bs[(lc+3)*128 + lr] = bv.w;
        __syncthreads();
#pragma unroll
        for (int k = 0; k < 8; k++) {
            float4 a0 = *(const float4*)&As[k*128 + ty*8];
            float4 a1 = *(const float4*)&As[k*128 + ty*8 + 4];
            float4 b0 = *(const float4*)&Bs[k*128 + tx*8];
            float4 b1 = *(const float4*)&Bs[k*128 + tx*8 + 4];
            float a[8] = {a0.x,a0.y,a0.z,a0.w,a1.x,a1.y,a1.z,a1.w};
            float b[8] = {b0.x,b0.y,b0.z,b0.w,b1.x,b1.y,b1.z,b1.w};
#pragma unroll
            for (int i = 0; i < 8; i++)
#pragma unroll
                for (int j = 0; j < 8; j++) acc[i][j] = fmaf(a[i], b[j], acc[i][j]);
        }
    }

#pragma unroll
    for (int i = 0; i < 8; i++) {
        int m = rowBase + ty*8 + i;
#pragma unroll
        for (int j = 0; j < 8; j++) {
            int n = colBase + tx*8 + j;
            C[m * 1024 + n] = acc[i][j];
        }
    }
}

// ---------------- causal flash attention ----------------
// grid: (S/64, NHEADS, BATCH), 256 threads, 52224B dynamic smem.
// Q tile 64x64 (pre-scaled 1/8), k-tiles of 64. P aliases the K buffer.
__global__ __launch_bounds__(256) void flash_kernel()
{
    extern __shared__ __align__(16) float smem[];
    const int LD = 68;
    float* Qs = smem;
    float* Ks = smem + 64*LD;   // aliased with Ps
    float* Ps = Ks;
    float* Vs = smem + 2*64*LD;

    const int t  = threadIdx.x;
    const int tx = t & 15, ty = t >> 4;
    const int qt = blockIdx.x, h = blockIdx.y, b = blockIdx.z;

    const float* Qb = g_Q + ((b*16 + h) * 2048) * 64;
    const float* Kb = g_K + ((b*16 + h) * 2048) * 64;
    const float* Vb = g_V + ((b*16 + h) * 2048) * 64;

    // load Q tile, pre-scaled by 1/sqrt(64)
#pragma unroll
    for (int it = 0; it < 4; it++) {
        int e = t + it*256;             // float4 index 0..1023
        int r = e >> 4, c = (e & 15) << 2;
        float4 v = *(const float4*)&Qb[(qt*64 + r)*64 + c];
        v.x *= 0.125f; v.y *= 0.125f; v.z *= 0.125f; v.w *= 0.125f;
        *(float4*)&Qs[r*LD + c] = v;
    }

    float m[4], l[4], acc[4][4];
#pragma unroll
    for (int i = 0; i < 4; i++) {
        m[i] = -1e30f; l[i] = 0.0f;
#pragma unroll
        for (int j = 0; j < 4; j++) acc[i][j] = 0.0f;
    }

    for (int kt = 0; kt <= qt; kt++) {
        __syncthreads();   // previous iteration's Ps/Vs reads done
#pragma unroll
        for (int it = 0; it < 4; it++) {
            int e = t + it*256;
            int r = e >> 4, c = (e & 15) << 2;
            *(float4*)&Ks[r*LD + c] = *(const float4*)&Kb[(kt*64 + r)*64 + c];
            *(float4*)&Vs[r*LD + c] = *(const float4*)&Vb[(kt*64 + r)*64 + c];
        }
        __syncthreads();

        // S = (Q/8) K^T   (64x64x64)
        float s[4][4];
#pragma unroll
        for (int i = 0; i < 4; i++)
#pragma unroll
            for (int j = 0; j < 4; j++) s[i][j] = 0.0f;

#pragma unroll 4
        for (int d4 = 0; d4 < 16; d4++) {
            float4 q[4], k[4];
#pragma unroll
            for (int i = 0; i < 4; i++) q[i] = *(const float4*)&Qs[(ty*4 + i)*LD + d4*4];
#pragma unroll
            for (int j = 0; j < 4; j++) k[j] = *(const float4*)&Ks[(tx*4 + j)*LD + d4*4];
#pragma unroll
            for (int i = 0; i < 4; i++)
#pragma unroll
                for (int j = 0; j < 4; j++) {
                    s[i][j] = fmaf(q[i].x, k[j].x, s[i][j]);
                    s[i][j] = fmaf(q[i].y, k[j].y, s[i][j]);
                    s[i][j] = fmaf(q[i].z, k[j].z, s[i][j]);
                    s[i][j] = fmaf(q[i].w, k[j].w, s[i][j]);
                }
        }

        if (kt == qt) {   // causal mask (diagonal tile only)
#pragma unroll
            for (int i = 0; i < 4; i++)
#pragma unroll
                for (int j = 0; j < 4; j++)
                    if (tx*4 + j > ty*4 + i) s[i][j] = -1e30f;
        }

        // online softmax
#pragma unroll
        for (int i = 0; i < 4; i++) {
            float tm = s[i][0];
            tm = fmaxf(tm, s[i][1]); tm = fmaxf(tm, s[i][2]); tm = fmaxf(tm, s[i][3]);
#pragma unroll
            for (int o = 8; o >= 1; o >>= 1)
                tm = fmaxf(tm, __shfl_xor_sync(0xffffffffu, tm, o, 16));
            float mn = fmaxf(m[i], tm);
            float alpha = __expf(m[i] - mn);
            m[i] = mn;
            float rs = 0.0f;
#pragma unroll
            for (int j = 0; j < 4; j++) { s[i][j] = __expf(s[i][j] - mn); rs += s[i][j]; }
#pragma unroll
            for (int o = 8; o >= 1; o >>= 1)
                rs += __shfl_xor_sync(0xffffffffu, rs, o, 16);
            l[i] = l[i]*alpha + rs;
#pragma unroll
            for (int j = 0; j < 4; j++) acc[i][j] *= alpha;
        }

        __syncthreads();   // all Ks reads done; safe to overwrite with P
#pragma unroll
        for (int i = 0; i < 4; i++)
#pragma unroll
            for (int j = 0; j < 4; j++)
                Ps[(ty*4 + i)*LD + tx*4 + j] = s[i][j];
        __syncthreads();

        // acc += P V   (64x64x64)
#pragma unroll 8
        for (int kk = 0; kk < 64; kk++) {
            float4 vv = *(const float4*)&Vs[kk*LD + tx*4];
            float p0 = Ps[(ty*4 + 0)*LD + kk];
            float p1 = Ps[(ty*4 + 1)*LD + kk];
            float p2 = Ps[(ty*4 + 2)*LD + kk];
            float p3 = Ps[(ty*4 + 3)*LD + kk];
            acc[0][0] = fmaf(p0, vv.x, acc[0][0]); acc[0][1] = fmaf(p0, vv.y, acc[0][1]);
            acc[0][2] = fmaf(p0, vv.z, acc[0][2]); acc[0][3] = fmaf(p0, vv.w, acc[0][3]);
            acc[1][0] = fmaf(p1, vv.x, acc[1][0]); acc[1][1] = fmaf(p1, vv.y, acc[1][1]);
            acc[1][2] = fmaf(p1, vv.z, acc[1][2]); acc[1][3] = fmaf(p1, vv.w, acc[1][3]);
            acc[2][0] = fmaf(p2, vv.x, acc[2][0]); acc[2][1] = fmaf(p2, vv.y, acc[2][1]);
            acc[2][2] = fmaf(p2, vv.z, acc[2][2]); acc[2][3] = fmaf(p2, vv.w, acc[2][3]);
            acc[3][0] = fmaf(p3, vv.x, acc[3][0]); acc[3][1] = fmaf(p3, vv.y, acc[3][1]);
            acc[3][2] = fmaf(p3, vv.z, acc[3][2]); acc[3][3] = fmaf(p3, vv.w, acc[3][3]);
        }
    }

    // write to [n][1024] layout for the output projection
#pragma unroll
    for (int i = 0; i < 4; i++) {
        float inv = 1.0f / l[i];
        int n = b*2048 + qt*64 + ty*4 + i;
#pragma unroll
        for (int j = 0; j < 4; j++)
            g_AO[n*1024 + h*64 + tx*4 + j] = acc[i][j] * inv;
    }
}

// ---------------- launch ----------------
extern "C" void kernel_launch(void* const* d_in, const int* in_sizes, int n_in,
                              void* d_out, int out_size) {
    (void)in_sizes; (void)n_in; (void)out_size;
    const float* x  = (const float*)d_in[0];
    const int*   tp = (const int*)d_in[1];
    const float* Wq = (const float*)d_in[2];
    const float* Wk = (const float*)d_in[3];
    const float* Wv = (const float*)d_in[4];
    const float* Wo = (const float*)d_in[5];
    float* out = (float*)d_out;

    float* ao;
    cudaGetSymbolAddress((void**)&ao, g_AO);

    rope_tables_kernel<<<(SEQ*(DK/2) + 255)/256, 256>>>(tp);

    dim3 gq(DMODEL/128, NROWS/128, 3);  // (8, 32, 3)
    qkv_gemm_kernel<<<gq, 256>>>(x, Wq, Wk, Wv);

    cudaFuncSetAttribute(flash_kernel, cudaFuncAttributeMaxDynamicSharedMemorySize, 52224);
    flash_kernel<<<dim3(SEQ/64, NHEADS, BATCH), 256, 52224>>>();

    dim3 go(DMODEL/128, NROWS/128);
    out_gemm_kernel<<<go, 256>>>(ao, Wo, out);
}

// round 7
// speedup vs baseline: 1.3992x; 1.3992x over previous
#include <cuda_runtime.h>
#include <cuda_bf16.h>
#include <math.h>
#include <stdint.h>

#define BATCH 2
#define SEQ   2048
#define DMODEL 1024
#define NHEADS 16
#define DK    64
#define NROWS (BATCH*SEQ)   // 4096

// ---------------- scratch (device globals; no allocation) ----------------
__device__ float g_Q[BATCH*NHEADS*SEQ*DK];   // [b][h][s][d]
__device__ float g_K[BATCH*NHEADS*SEQ*DK];
__device__ float g_V[BATCH*NHEADS*SEQ*DK];
__device__ float g_AO[NROWS*DMODEL];         // attention output, [n][1024]
__device__ float g_cos[SEQ*(DK/2)];
__device__ float g_sin[SEQ*(DK/2)];

// ---------------- RoPE tables ----------------
__global__ void rope_tables_kernel(const int* __restrict__ pos) {
    int i = blockIdx.x * blockDim.x + threadIdx.x;
    if (i >= SEQ * (DK/2)) return;
    int s = i >> 5;        // / 32
    int p = i & 31;
    float inv_freq = powf(10000.0f, -(2.0f * (float)p) / 64.0f);
    float ang = (float)pos[s] * inv_freq;
    g_cos[i] = cosf(ang);
    g_sin[i] = sinf(ang);
}

// ---------------- tf32 mma helpers ----------------
__device__ __forceinline__ uint32_t f2tf(float x) {
    uint32_t y;
    asm("cvt.rna.tf32.f32 %0, %1;" : "=r"(y) : "f"(x));
    return y;
}

__device__ __forceinline__ void mma_tf32(
    float& c0, float& c1, float& c2, float& c3,
    uint32_t a0, uint32_t a1, uint32_t a2, uint32_t a3,
    uint32_t b0, uint32_t b1)
{
    asm volatile(
        "mma.sync.aligned.m16n8k8.row.col.f32.tf32.tf32.f32 "
        "{%0,%1,%2,%3},{%4,%5,%6,%7},{%8,%9},{%0,%1,%2,%3};\n"
        : "+f"(c0), "+f"(c1), "+f"(c2), "+f"(c3)
        : "r"(a0), "r"(a1), "r"(a2), "r"(a3), "r"(b0), "r"(b1));
}

#define LDT 36   // 32 + 4 pad: fragment-load bank = (4g+tg)%32, conflict-free

// Shared mainloop: computes a 128x128 tile of C = A * W^T (both row-major, K=1024)
// Accumulators: acc[mi][ni][4] per thread, warp tile 64x32, 2x4 warp grid.
#define GEMM_TF32_MAINLOOP(Aptr, Wptr)                                          \
    __shared__ uint32_t As[128*LDT];                                            \
    __shared__ uint32_t Bs[128*LDT];                                            \
    const int t    = threadIdx.x;                                               \
    const int lane = t & 31, wid = t >> 5;                                      \
    const int warp_m = (wid >> 2) * 64;                                         \
    const int warp_n = (wid & 3) * 32;                                          \
    const int rowBase = blockIdx.y * 128;                                       \
    const int colBase = blockIdx.x * 128;                                       \
    const int g  = lane >> 2;                                                   \
    const int tg = lane & 3;                                                    \
    float acc[4][4][4];                                                         \
    _Pragma("unroll") for (int mi = 0; mi < 4; mi++)                            \
    _Pragma("unroll") for (int ni = 0; ni < 4; ni++)                            \
    _Pragma("unroll") for (int r = 0; r < 4; r++) acc[mi][ni][r] = 0.0f;        \
    for (int k0 = 0; k0 < 1024; k0 += 32) {                                     \
        float4 av[4], bv[4];                                                    \
        _Pragma("unroll")                                                       \
        for (int it = 0; it < 4; it++) {                                        \
            int e = t + it*256;                                                 \
            int r = e >> 3, c = (e & 7) * 4;                                    \
            av[it] = *(const float4*)&(Aptr)[(rowBase + r)*1024 + k0 + c];      \
            bv[it] = *(const float4*)&(Wptr)[(colBase + r)*1024 + k0 + c];      \
        }                                                                       \
        __syncthreads();                                                        \
        _Pragma("unroll")                                                       \
        for (int it = 0; it < 4; it++) {                                        \
            int e = t + it*256;                                                 \
            int r = e >> 3, c = (e & 7) * 4;                                    \
            uint4 ua = { f2tf(av[it].x), f2tf(av[it].y), f2tf(av[it].z), f2tf(av[it].w) }; \
            uint4 ub = { f2tf(bv[it].x), f2tf(bv[it].y), f2tf(bv[it].z), f2tf(bv[it].w) }; \
            *(uint4*)&As[r*LDT + c] = ua;                                       \
            *(uint4*)&Bs[r*LDT + c] = ub;                                       \
        }                                                                       \
        __syncthreads();                                                        \
        _Pragma("unroll")                                                       \
        for (int ks = 0; ks < 4; ks++) {                                        \
            uint32_t af[4][4], bf[4][2];                                        \
            _Pragma("unroll")                                                   \
            for (int mi = 0; mi < 4; mi++) {                                    \
                int r0 = warp_m + mi*16 + g;                                    \
                af[mi][0] = As[r0*LDT     + ks*8 + tg];                         \
                af[mi][1] = As[(r0+8)*LDT + ks*8 + tg];                         \
                af[mi][2] = As[r0*LDT     + ks*8 + tg + 4];                     \
                af[mi][3] = As[(r0+8)*LDT + ks*8 + tg + 4];                     \
            }                                                                   \
            _Pragma("unroll")                                                   \
            for (int ni = 0; ni < 4; ni++) {                                    \
                int r0 = warp_n + ni*8 + g;                                     \
                bf[ni][0] = Bs[r0*LDT + ks*8 + tg];                             \
                bf[ni][1] = Bs[r0*LDT + ks*8 + tg + 4];                         \
            }                                                                   \
            _Pragma("unroll")                                                   \
            for (int mi = 0; mi < 4; mi++)                                      \
            _Pragma("unroll")                                                   \
            for (int ni = 0; ni < 4; ni++)                                      \
                mma_tf32(acc[mi][ni][0], acc[mi][ni][1], acc[mi][ni][2], acc[mi][ni][3], \
                         af[mi][0], af[mi][1], af[mi][2], af[mi][3],            \
                         bf[ni][0], bf[ni][1]);                                 \
        }                                                                       \
    }

// ---------------- fused QKV projection (tf32 mma + RoPE epilogue) ----------------
__global__ __launch_bounds__(256) void qkv_mma_kernel(
    const float* __restrict__ A,
    const float* __restrict__ Wq, const float* __restrict__ Wk, const float* __restrict__ Wv)
{
    const int which = blockIdx.z;
    const float* W = (which == 0) ? Wq : (which == 1) ? Wk : Wv;
    float* C = (which == 0) ? g_Q : (which == 1) ? g_K : g_V;
    const bool do_rope = (which < 2);

    GEMM_TF32_MAINLOOP(A, W)

    // epilogue: (c_even, c_odd) register pair == RoPE pair, scatter to [b][h][s][d]
#pragma unroll
    for (int mi = 0; mi < 4; mi++) {
#pragma unroll
        for (int half = 0; half < 2; half++) {
            int m  = rowBase + warp_m + mi*16 + g + half*8;
            int b_ = m >> 11;
            int s_ = m & 2047;
#pragma unroll
            for (int ni = 0; ni < 4; ni++) {
                int n = colBase + warp_n + ni*8 + tg*2;   // always even
                float v0 = acc[mi][ni][half*2 + 0];
                float v1 = acc[mi][ni][half*2 + 1];
                if (do_rope) {
                    int p = (n & 63) >> 1;
                    float cth = g_cos[s_*32 + p];
                    float sth = g_sin[s_*32 + p];
                    float r1 = v0*cth - v1*sth;
                    float r2 = v0*sth + v1*cth;
                    v0 = r1; v1 = r2;
                }
                int h = n >> 6, d = n & 63;
                float2 o; o.x = v0; o.y = v1;
                *(float2*)&C[((((b_ << 4) + h) * 2048 + s_) * 64) + d] = o;
            }
        }
    }
}

// ---------------- output projection (tf32 mma, row-major store) ----------------
__global__ __launch_bounds__(256) void out_mma_kernel(
    const float* __restrict__ A, const float* __restrict__ W, float* __restrict__ Cg)
{
    GEMM_TF32_MAINLOOP(A, W)

#pragma unroll
    for (int mi = 0; mi < 4; mi++) {
#pragma unroll
        for (int half = 0; half < 2; half++) {
            int m = rowBase + warp_m + mi*16 + g + half*8;
#pragma unroll
            for (int ni = 0; ni < 4; ni++) {
                int n = colBase + warp_n + ni*8 + tg*2;
                float2 o;
                o.x = acc[mi][ni][half*2 + 0];
                o.y = acc[mi][ni][half*2 + 1];
                *(float2*)&Cg[m*1024 + n] = o;
            }
        }
    }
}

// ---------------- causal flash attention (unchanged fp32) ----------------
// grid: (S/64, NHEADS, BATCH), 256 threads, 52224B dynamic smem.
__global__ __launch_bounds__(256) void flash_kernel()
{
    extern __shared__ __align__(16) float smem[];
    const int LD = 68;
    float* Qs = smem;
    float* Ks = smem + 64*LD;   // aliased with Ps
    float* Ps = Ks;
    float* Vs = smem + 2*64*LD;

    const int t  = threadIdx.x;
    const int tx = t & 15, ty = t >> 4;
    const int qt = blockIdx.x, h = blockIdx.y, b = blockIdx.z;

    const float* Qb = g_Q + ((b*16 + h) * 2048) * 64;
    const float* Kb = g_K + ((b*16 + h) * 2048) * 64;
    const float* Vb = g_V + ((b*16 + h) * 2048) * 64;

#pragma unroll
    for (int it = 0; it < 4; it++) {
        int e = t + it*256;
        int r = e >> 4, c = (e & 15) << 2;
        float4 v = *(const float4*)&Qb[(qt*64 + r)*64 + c];
        v.x *= 0.125f; v.y *= 0.125f; v.z *= 0.125f; v.w *= 0.125f;
        *(float4*)&Qs[r*LD + c] = v;
    }

    float m[4], l[4], acc[4][4];
#pragma unroll
    for (int i = 0; i < 4; i++) {
        m[i] = -1e30f; l[i] = 0.0f;
#pragma unroll
        for (int j = 0; j < 4; j++) acc[i][j] = 0.0f;
    }

    for (int kt = 0; kt <= qt; kt++) {
        __syncthreads();
#pragma unroll
        for (int it = 0; it < 4; it++) {
            int e = t + it*256;
            int r = e >> 4, c = (e & 15) << 2;
            *(float4*)&Ks[r*LD + c] = *(const float4*)&Kb[(kt*64 + r)*64 + c];
            *(float4*)&Vs[r*LD + c] = *(const float4*)&Vb[(kt*64 + r)*64 + c];
        }
        __syncthreads();

        float s[4][4];
#pragma unroll
        for (int i = 0; i < 4; i++)
#pragma unroll
            for (int j = 0; j < 4; j++) s[i][j] = 0.0f;

#pragma unroll 4
        for (int d4 = 0; d4 < 16; d4++) {
            float4 q[4], k[4];
#pragma unroll
            for (int i = 0; i < 4; i++) q[i] = *(const float4*)&Qs[(ty*4 + i)*LD + d4*4];
#pragma unroll
            for (int j = 0; j < 4; j++) k[j] = *(const float4*)&Ks[(tx*4 + j)*LD + d4*4];
#pragma unroll
            for (int i = 0; i < 4; i++)
#pragma unroll
                for (int j = 0; j < 4; j++) {
                    s[i][j] = fmaf(q[i].x, k[j].x, s[i][j]);
                    s[i][j] = fmaf(q[i].y, k[j].y, s[i][j]);
                    s[i][j] = fmaf(q[i].z, k[j].z, s[i][j]);
                    s[i][j] = fmaf(q[i].w, k[j].w, s[i][j]);
                }
        }

        if (kt == qt) {
#pragma unroll
            for (int i = 0; i < 4; i++)
#pragma unroll
                for (int j = 0; j < 4; j++)
                    if (tx*4 + j > ty*4 + i) s[i][j] = -1e30f;
        }

#pragma unroll
        for (int i = 0; i < 4; i++) {
            float tm = s[i][0];
            tm = fmaxf(tm, s[i][1]); tm = fmaxf(tm, s[i][2]); tm = fmaxf(tm, s[i][3]);
#pragma unroll
            for (int o = 8; o >= 1; o >>= 1)
                tm = fmaxf(tm, __shfl_xor_sync(0xffffffffu, tm, o, 16));
            float mn = fmaxf(m[i], tm);
            float alpha = __expf(m[i] - mn);
            m[i] = mn;
            float rs = 0.0f;
#pragma unroll
            for (int j = 0; j < 4; j++) { s[i][j] = __expf(s[i][j] - mn); rs += s[i][j]; }
#pragma unroll
            for (int o = 8; o >= 1; o >>= 1)
                rs += __shfl_xor_sync(0xffffffffu, rs, o, 16);
            l[i] = l[i]*alpha + rs;
#pragma unroll
            for (int j = 0; j < 4; j++) acc[i][j] *= alpha;
        }

        __syncthreads();
#pragma unroll
        for (int i = 0; i < 4; i++)
#pragma unroll
            for (int j = 0; j < 4; j++)
                Ps[(ty*4 + i)*LD + tx*4 + j] = s[i][j];
        __syncthreads();

#pragma unroll 8
        for (int kk = 0; kk < 64; kk++) {
            float4 vv = *(const float4*)&Vs[kk*LD + tx*4];
            float p0 = Ps[(ty*4 + 0)*LD + kk];
            float p1 = Ps[(ty*4 + 1)*LD + kk];
            float p2 = Ps[(ty*4 + 2)*LD + kk];
            float p3 = Ps[(ty*4 + 3)*LD + kk];
            acc[0][0] = fmaf(p0, vv.x, acc[0][0]); acc[0][1] = fmaf(p0, vv.y, acc[0][1]);
            acc[0][2] = fmaf(p0, vv.z, acc[0][2]); acc[0][3] = fmaf(p0, vv.w, acc[0][3]);
            acc[1][0] = fmaf(p1, vv.x, acc[1][0]); acc[1][1] = fmaf(p1, vv.y, acc[1][1]);
            acc[1][2] = fmaf(p1, vv.z, acc[1][2]); acc[1][3] = fmaf(p1, vv.w, acc[1][3]);
            acc[2][0] = fmaf(p2, vv.x, acc[2][0]); acc[2][1] = fmaf(p2, vv.y, acc[2][1]);
            acc[2][2] = fmaf(p2, vv.z, acc[2][2]); acc[2][3] = fmaf(p2, vv.w, acc[2][3]);
            acc[3][0] = fmaf(p3, vv.x, acc[3][0]); acc[3][1] = fmaf(p3, vv.y, acc[3][1]);
            acc[3][2] = fmaf(p3, vv.z, acc[3][2]); acc[3][3] = fmaf(p3, vv.w, acc[3][3]);
        }
    }

#pragma unroll
    for (int i = 0; i < 4; i++) {
        float inv = 1.0f / l[i];
        int n = b*2048 + qt*64 + ty*4 + i;
#pragma unroll
        for (int j = 0; j < 4; j++)
            g_AO[n*1024 + h*64 + tx*4 + j] = acc[i][j] * inv;
    }
}

// ---------------- launch ----------------
extern "C" void kernel_launch(void* const* d_in, const int* in_sizes, int n_in,
                              void* d_out, int out_size) {
    (void)in_sizes; (void)n_in; (void)out_size;
    const float* x  = (const float*)d_in[0];
    const int*   tp = (const int*)d_in[1];
    const float* Wq = (const float*)d_in[2];
    const float* Wk = (const float*)d_in[3];
    const float* Wv = (const float*)d_in[4];
    const float* Wo = (const float*)d_in[5];
    float* out = (float*)d_out;

    float* ao;
    cudaGetSymbolAddress((void**)&ao, g_AO);

    rope_tables_kernel<<<(SEQ*(DK/2) + 255)/256, 256>>>(tp);

    dim3 gq(DMODEL/128, NROWS/128, 3);  // (8, 32, 3)
    qkv_mma_kernel<<<gq, 256>>>(x, Wq, Wk, Wv);

    cudaFuncSetAttribute(flash_kernel, cudaFuncAttributeMaxDynamicSharedMemorySize, 52224);
    flash_kernel<<<dim3(SEQ/64, NHEADS, BATCH), 256, 52224>>>();

    dim3 go(DMODEL/128, NROWS/128);
    out_mma_kernel<<<go, 256>>>(ao, Wo, out);
}

// round 8
// speedup vs baseline: 3.2950x; 2.3549x over previous
#include <cuda_runtime.h>
#include <cuda_bf16.h>
#include <math.h>
#include <stdint.h>

#define BATCH 2
#define SEQ   2048
#define DMODEL 1024
#define NHEADS 16
#define DK    64
#define NROWS (BATCH*SEQ)   // 4096

// ---------------- scratch (device globals; no allocation) ----------------
__device__ float g_Q[BATCH*NHEADS*SEQ*DK];    // [b][h][s][d]
__device__ float g_K[BATCH*NHEADS*SEQ*DK];    // [b][h][s][d]
__device__ float g_Vt[BATCH*NHEADS*DK*SEQ];   // [b][h][d][s]  (transposed!)
__device__ float g_AO[NROWS*DMODEL];          // attention output, [n][1024]
__device__ float g_cos[SEQ*(DK/2)];
__device__ float g_sin[SEQ*(DK/2)];

// ---------------- RoPE tables ----------------
__global__ void rope_tables_kernel(const int* __restrict__ pos) {
    int i = blockIdx.x * blockDim.x + threadIdx.x;
    if (i >= SEQ * (DK/2)) return;
    int s = i >> 5;        // / 32
    int p = i & 31;
    float inv_freq = powf(10000.0f, -(2.0f * (float)p) / 64.0f);
    float ang = (float)pos[s] * inv_freq;
    g_cos[i] = cosf(ang);
    g_sin[i] = sinf(ang);
}

// ---------------- tf32 mma helpers ----------------
__device__ __forceinline__ uint32_t f2tf(float x) {
    uint32_t y;
    asm("cvt.rna.tf32.f32 %0, %1;" : "=r"(y) : "f"(x));
    return y;
}

__device__ __forceinline__ void mma_tf32(
    float& c0, float& c1, float& c2, float& c3,
    uint32_t a0, uint32_t a1, uint32_t a2, uint32_t a3,
    uint32_t b0, uint32_t b1)
{
    asm volatile(
        "mma.sync.aligned.m16n8k8.row.col.f32.tf32.tf32.f32 "
        "{%0,%1,%2,%3},{%4,%5,%6,%7},{%8,%9},{%0,%1,%2,%3};\n"
        : "+f"(c0), "+f"(c1), "+f"(c2), "+f"(c3)
        : "r"(a0), "r"(a1), "r"(a2), "r"(a3), "r"(b0), "r"(b1));
}

#define LDT 36   // 32 + 4 pad: fragment-load bank = (4g+tg)%32, conflict-free

// Shared mainloop: computes a 128x128 tile of C = A * W^T (both row-major, K=1024)
#define GEMM_TF32_MAINLOOP(Aptr, Wptr)                                          \
    __shared__ uint32_t As[128*LDT];                                            \
    __shared__ uint32_t Bs[128*LDT];                                            \
    const int t    = threadIdx.x;                                               \
    const int lane = t & 31, wid = t >> 5;                                      \
    const int warp_m = (wid >> 2) * 64;                                         \
    const int warp_n = (wid & 3) * 32;                                          \
    const int rowBase = blockIdx.y * 128;                                       \
    const int colBase = blockIdx.x * 128;                                       \
    const int g  = lane >> 2;                                                   \
    const int tg = lane & 3;                                                    \
    float acc[4][4][4];                                                         \
    _Pragma("unroll") for (int mi = 0; mi < 4; mi++)                            \
    _Pragma("unroll") for (int ni = 0; ni < 4; ni++)                            \
    _Pragma("unroll") for (int r = 0; r < 4; r++) acc[mi][ni][r] = 0.0f;        \
    for (int k0 = 0; k0 < 1024; k0 += 32) {                                     \
        float4 av[4], bv[4];                                                    \
        _Pragma("unroll")                                                       \
        for (int it = 0; it < 4; it++) {                                        \
            int e = t + it*256;                                                 \
            int r = e >> 3, c = (e & 7) * 4;                                    \
            av[it] = *(const float4*)&(Aptr)[(rowBase + r)*1024 + k0 + c];      \
            bv[it] = *(const float4*)&(Wptr)[(colBase + r)*1024 + k0 + c];      \
        }                                                                       \
        __syncthreads();                                                        \
        _Pragma("unroll")                                                       \
        for (int it = 0; it < 4; it++) {                                        \
            int e = t + it*256;                                                 \
            int r = e >> 3, c = (e & 7) * 4;                                    \
            uint4 ua = { f2tf(av[it].x), f2tf(av[it].y), f2tf(av[it].z), f2tf(av[it].w) }; \
            uint4 ub = { f2tf(bv[it].x), f2tf(bv[it].y), f2tf(bv[it].z), f2tf(bv[it].w) }; \
            *(uint4*)&As[r*LDT + c] = ua;                                       \
            *(uint4*)&Bs[r*LDT + c] = ub;                                       \
        }                                                                       \
        __syncthreads();                                                        \
        _Pragma("unroll")                                                       \
        for (int ks = 0; ks < 4; ks++) {                                        \
            uint32_t af[4][4], bf[4][2];                                        \
            _Pragma("unroll")                                                   \
            for (int mi = 0; mi < 4; mi++) {                                    \
                int r0 = warp_m + mi*16 + g;                                    \
                af[mi][0] = As[r0*LDT     + ks*8 + tg];                         \
                af[mi][1] = As[(r0+8)*LDT + ks*8 + tg];                         \
                af[mi][2] = As[r0*LDT     + ks*8 + tg + 4];                     \
                af[mi][3] = As[(r0+8)*LDT + ks*8 + tg + 4];                     \
            }                                                                   \
            _Pragma("unroll")                                                   \
            for (int ni = 0; ni < 4; ni++) {                                    \
                int r0 = warp_n + ni*8 + g;                                     \
                bf[ni][0] = Bs[r0*LDT + ks*8 + tg];                             \
                bf[ni][1] = Bs[r0*LDT + ks*8 + tg + 4];                         \
            }                                                                   \
            _Pragma("unroll")                                                   \
            for (int mi = 0; mi < 4; mi++)                                      \
            _Pragma("unroll")                                                   \
            for (int ni = 0; ni < 4; ni++)                                      \
                mma_tf32(acc[mi][ni][0], acc[mi][ni][1], acc[mi][ni][2], acc[mi][ni][3], \
                         af[mi][0], af[mi][1], af[mi][2], af[mi][3],            \
                         bf[ni][0], bf[ni][1]);                                 \
        }                                                                       \
    }

// ---------------- fused QKV projection (tf32 mma + RoPE epilogue) ----------------
__global__ __launch_bounds__(256) void qkv_mma_kernel(
    const float* __restrict__ A,
    const float* __restrict__ Wq, const float* __restrict__ Wk, const float* __restrict__ Wv)
{
    const int which = blockIdx.z;
    const float* W = (which == 0) ? Wq : (which == 1) ? Wk : Wv;
    float* C = (which == 0) ? g_Q : (which == 1) ? g_K : g_Vt;
    const bool do_rope = (which < 2);

    GEMM_TF32_MAINLOOP(A, W)

#pragma unroll
    for (int mi = 0; mi < 4; mi++) {
#pragma unroll
        for (int half = 0; half < 2; half++) {
            int m  = rowBase + warp_m + mi*16 + g + half*8;
            int b_ = m >> 11;
            int s_ = m & 2047;
#pragma unroll
            for (int ni = 0; ni < 4; ni++) {
                int n = colBase + warp_n + ni*8 + tg*2;   // always even
                float v0 = acc[mi][ni][half*2 + 0];
                float v1 = acc[mi][ni][half*2 + 1];
                int hh = n >> 6, d = n & 63;
                if (do_rope) {
                    int p = d >> 1;
                    float cth = g_cos[s_*32 + p];
                    float sth = g_sin[s_*32 + p];
                    float r1 = v0*cth - v1*sth;
                    float r2 = v0*sth + v1*cth;
                    float2 o; o.x = r1; o.y = r2;
                    *(float2*)&C[((((b_ << 4) + hh) * 2048 + s_) * 64) + d] = o;
                } else {
                    // V: store transposed [b][h][d][s]
                    float* base = C + (((b_ << 4) + hh) * 64 + d) * 2048 + s_;
                    base[0]    = v0;
                    base[2048] = v1;
                }
            }
        }
    }
}

// ---------------- output projection (tf32 mma, row-major store) ----------------
__global__ __launch_bounds__(256) void out_mma_kernel(
    const float* __restrict__ A, const float* __restrict__ W, float* __restrict__ Cg)
{
    GEMM_TF32_MAINLOOP(A, W)

#pragma unroll
    for (int mi = 0; mi < 4; mi++) {
#pragma unroll
        for (int half = 0; half < 2; half++) {
            int m = rowBase + warp_m + mi*16 + g + half*8;
#pragma unroll
            for (int ni = 0; ni < 4; ni++) {
                int n = colBase + warp_n + ni*8 + tg*2;
                float2 o;
                o.x = acc[mi][ni][half*2 + 0];
                o.y = acc[mi][ni][half*2 + 1];
                *(float2*)&Cg[m*1024 + n] = o;
            }
        }
    }
}

// ---------------- causal flash attention, tf32 mma ----------------
// Br=128 (8 warps x m16), Bc=64. QK^T uses 3xTF32 split; PV single tf32.
// smem: Qh[128x68] Ql[128x68] (Kh[64x68]+Kl[64x68] aliased with P[128x68]) Vt[64x68]
#define FLD 68
#define FLASH_SMEM_BYTES ((8704*3 + 4352) * 4)   // 121856

__global__ __launch_bounds__(256, 1) void flash_mma_kernel()
{
    extern __shared__ uint32_t smu[];
    uint32_t* Qh = smu;                 // 128*68 = 8704
    uint32_t* Ql = smu + 8704;
    uint32_t* Kh = smu + 17408;         // 64*68 = 4352
    uint32_t* Kl = smu + 17408 + 4352;
    uint32_t* Ps = smu + 17408;         // alias over Kh+Kl (128*68)
    uint32_t* Vs = smu + 26112;         // 64*68

    const int t = threadIdx.x, lane = t & 31, wid = t >> 5;
    const int g = lane >> 2, tg = lane & 3;
    const int qt = gridDim.x - 1 - blockIdx.x;   // heavy tiles first
    const int h = blockIdx.y, b = blockIdx.z;
    const int warp_m = wid * 16;

    const float* Qg = g_Q  + ((b*16 + h)*2048 + qt*128) * 64;
    const float* Kg = g_K  + ((b*16 + h)*2048) * 64;
    const float* Vg = g_Vt + (b*16 + h) * 64 * 2048;

    const float qs = 0.125f * 1.4426950408889634f;   // 1/sqrt(dk) * log2(e)

    // load Q tile (128x64), scale, split hi/lo
#pragma unroll
    for (int it = 0; it < 8; it++) {
        int e = t + it*256;
        int r = e >> 4, c = (e & 15) * 4;
        float4 v = *(const float4*)&Qg[r*64 + c];
        v.x *= qs; v.y *= qs; v.z *= qs; v.w *= qs;
        uint4 hi, lo;
        hi.x = f2tf(v.x); lo.x = f2tf(v.x - __uint_as_float(hi.x));
        hi.y = f2tf(v.y); lo.y = f2tf(v.y - __uint_as_float(hi.y));
        hi.z = f2tf(v.z); lo.z = f2tf(v.z - __uint_as_float(hi.z));
        hi.w = f2tf(v.w); lo.w = f2tf(v.w - __uint_as_float(hi.w));
        *(uint4*)&Qh[r*FLD + c] = hi;
        *(uint4*)&Ql[r*FLD + c] = lo;
    }

    float o[8][4];
#pragma unroll
    for (int ni = 0; ni < 8; ni++)
#pragma unroll
        for (int r = 0; r < 4; r++) o[ni][r] = 0.0f;
    float mrow[2] = {-1e30f, -1e30f};
    float lrow[2] = {0.0f, 0.0f};

    const int nkt = 2*qt + 2;
    for (int kt = 0; kt < nkt; kt++) {
        __syncthreads();   // prior P/V reads complete
#pragma unroll
        for (int it = 0; it < 4; it++) {
            int e = t + it*256;
            int r = e >> 4, c = (e & 15) * 4;
            float4 kv = *(const float4*)&Kg[(kt*64 + r)*64 + c];
            uint4 hi, lo;
            hi.x = f2tf(kv.x); lo.x = f2tf(kv.x - __uint_as_float(hi.x));
            hi.y = f2tf(kv.y); lo.y = f2tf(kv.y - __uint_as_float(hi.y));
            hi.z = f2tf(kv.z); lo.z = f2tf(kv.z - __uint_as_float(hi.z));
            hi.w = f2tf(kv.w); lo.w = f2tf(kv.w - __uint_as_float(hi.w));
            *(uint4*)&Kh[r*FLD + c] = hi;
            *(uint4*)&Kl[r*FLD + c] = lo;
            float4 vv = *(const float4*)&Vg[r*2048 + kt*64 + c];
            uint4 vt;
            vt.x = f2tf(vv.x); vt.y = f2tf(vv.y); vt.z = f2tf(vv.z); vt.w = f2tf(vv.w);
            *(uint4*)&Vs[r*FLD + c] = vt;
        }
        __syncthreads();

        // S = Q K^T with 3xTF32 split
        float s[8][4];
#pragma unroll
        for (int ni = 0; ni < 8; ni++)
#pragma unroll
            for (int r = 0; r < 4; r++) s[ni][r] = 0.0f;

#pragma unroll
        for (int ks = 0; ks < 8; ks++) {
            int ra = (warp_m + g)*FLD + ks*8 + tg;
            int rb = (warp_m + g + 8)*FLD + ks*8 + tg;
            uint32_t ah0 = Qh[ra], ah1 = Qh[rb], ah2 = Qh[ra+4], ah3 = Qh[rb+4];
            uint32_t al0 = Ql[ra], al1 = Ql[rb], al2 = Ql[ra+4], al3 = Ql[rb+4];
#pragma unroll
            for (int ni = 0; ni < 8; ni++) {
                int rk = (ni*8 + g)*FLD + ks*8 + tg;
                uint32_t bh0 = Kh[rk], bh1 = Kh[rk+4];
                uint32_t bl0 = Kl[rk], bl1 = Kl[rk+4];
                mma_tf32(s[ni][0], s[ni][1], s[ni][2], s[ni][3], ah0, ah1, ah2, ah3, bh0, bh1);
                mma_tf32(s[ni][0], s[ni][1], s[ni][2], s[ni][3], al0, al1, al2, al3, bh0, bh1);
                mma_tf32(s[ni][0], s[ni][1], s[ni][2], s[ni][3], ah0, ah1, ah2, ah3, bl0, bl1);
            }
        }

        // causal mask (only tiles touching the diagonal)
        if (kt*64 + 63 > qt*128 + warp_m) {
            int r0 = qt*128 + warp_m + g;
#pragma unroll
            for (int ni = 0; ni < 8; ni++) {
                int col = kt*64 + ni*8 + 2*tg;
                if (col   > r0)     s[ni][0] = -1e30f;
                if (col+1 > r0)     s[ni][1] = -1e30f;
                if (col   > r0 + 8) s[ni][2] = -1e30f;
                if (col+1 > r0 + 8) s[ni][3] = -1e30f;
            }
        }

        // online softmax (log2 domain; exp2f = bare MUFU.EX2)
#pragma unroll
        for (int r = 0; r < 2; r++) {
            float tm = -1e30f;
#pragma unroll
            for (int ni = 0; ni < 8; ni++)
                tm = fmaxf(tm, fmaxf(s[ni][2*r], s[ni][2*r+1]));
            tm = fmaxf(tm, __shfl_xor_sync(0xffffffffu, tm, 1));
            tm = fmaxf(tm, __shfl_xor_sync(0xffffffffu, tm, 2));
            float mn = fmaxf(mrow[r], tm);
            float alpha = exp2f(mrow[r] - mn);
            mrow[r] = mn;
            float rs = 0.0f;
#pragma unroll
            for (int ni = 0; ni < 8; ni++) {
                s[ni][2*r]   = exp2f(s[ni][2*r]   - mn);
                s[ni][2*r+1] = exp2f(s[ni][2*r+1] - mn);
                rs += s[ni][2*r] + s[ni][2*r+1];
            }
            rs += __shfl_xor_sync(0xffffffffu, rs, 1);
            rs += __shfl_xor_sync(0xffffffffu, rs, 2);
            lrow[r] = lrow[r]*alpha + rs;
#pragma unroll
            for (int ni = 0; ni < 8; ni++) { o[ni][2*r] *= alpha; o[ni][2*r+1] *= alpha; }
        }

        __syncthreads();   // all K fragment reads finished; safe to overwrite with P
#pragma unroll
        for (int ni = 0; ni < 8; ni++) {
            uint2 p0, p1;
            p0.x = f2tf(s[ni][0]); p0.y = f2tf(s[ni][1]);
            p1.x = f2tf(s[ni][2]); p1.y = f2tf(s[ni][3]);
            *(uint2*)&Ps[(warp_m + g)*FLD     + ni*8 + 2*tg] = p0;
            *(uint2*)&Ps[(warp_m + g + 8)*FLD + ni*8 + 2*tg] = p1;
        }
        __syncthreads();

        // O += P * V   (A = P [m16 x k64], B = Vt [n=dk][k=seq])
#pragma unroll
        for (int ks = 0; ks < 8; ks++) {
            int ra = (warp_m + g)*FLD + ks*8 + tg;
            int rb = (warp_m + g + 8)*FLD + ks*8 + tg;
            uint32_t a0 = Ps[ra], a1 = Ps[rb], a2 = Ps[ra+4], a3 = Ps[rb+4];
#pragma unroll
            for (int ni = 0; ni < 8; ni++) {
                int rv = (ni*8 + g)*FLD + ks*8 + tg;
                uint32_t b0 = Vs[rv], b1 = Vs[rv+4];
                mma_tf32(o[ni][0], o[ni][1], o[ni][2], o[ni][3], a0, a1, a2, a3, b0, b1);
            }
        }
    }

    // epilogue -> g_AO [n][1024]
    float inv0 = 1.0f / lrow[0];
    float inv1 = 1.0f / lrow[1];
    int base0 = (b*2048 + qt*128 + warp_m + g) * 1024 + h*64;
#pragma unroll
    for (int ni = 0; ni < 8; ni++) {
        int cc = ni*8 + 2*tg;
        float2 w0, w1;
        w0.x = o[ni][0]*inv0; w0.y = o[ni][1]*inv0;
        w1.x = o[ni][2]*inv1; w1.y = o[ni][3]*inv1;
        *(float2*)&g_AO[base0 + cc]          = w0;
        *(float2*)&g_AO[base0 + 8*1024 + cc] = w1;
    }
}

// ---------------- launch ----------------
extern "C" void kernel_launch(void* const* d_in, const int* in_sizes, int n_in,
                              void* d_out, int out_size) {
    (void)in_sizes; (void)n_in; (void)out_size;
    const float* x  = (const float*)d_in[0];
    const int*   tp = (const int*)d_in[1];
    const float* Wq = (const float*)d_in[2];
    const float* Wk = (const float*)d_in[3];
    const float* Wv = (const float*)d_in[4];
    const float* Wo = (const float*)d_in[5];
    float* out = (float*)d_out;

    float* ao;
    cudaGetSymbolAddress((void**)&ao, g_AO);

    rope_tables_kernel<<<(SEQ*(DK/2) + 255)/256, 256>>>(tp);

    dim3 gq(DMODEL/128, NROWS/128, 3);  // (8, 32, 3)
    qkv_mma_kernel<<<gq, 256>>>(x, Wq, Wk, Wv);

    cudaFuncSetAttribute(flash_mma_kernel, cudaFuncAttributeMaxDynamicSharedMemorySize, FLASH_SMEM_BYTES);
    flash_mma_kernel<<<dim3(SEQ/128, NHEADS, BATCH), 256, FLASH_SMEM_BYTES>>>();

    dim3 go(DMODEL/128, NROWS/128);
    out_mma_kernel<<<go, 256>>>(ao, Wo, out);
}